// round 2
// baseline (speedup 1.0000x reference)
#include <cuda_runtime.h>
#include <cstdint>

// Problem shape (fixed by setup_inputs)
#define D_IN   2048
#define D_SAE  16384
#define NROWS  8192
#define KTOP   64

// Scratch (static device globals -- allocation-free per harness rules)
__device__ float g_pre[(size_t)NROWS * D_SAE];   // 512 MB pre-activations
__device__ int   g_idx[NROWS * KTOP];
__device__ float g_val[NROWS * KTOP];

// ---------------------------------------------------------------------------
// K1: fp32 SGEMM  C = A @ B + bias
//     A = x      [M, K]  row-major (M=8192, K=2048)
//     B = W_enc  [K, N]  row-major (N=16384)
//     C = g_pre  [M, N]
// 128x128 block tile, BK=16, 256 threads, 8x8 per-thread micro-tile.
// ---------------------------------------------------------------------------
#define BM 128
#define BN 128
#define BK 16
#define TM 8
#define TN 8

__global__ __launch_bounds__(256) void sgemm_bias_kernel(
    const float* __restrict__ A,
    const float* __restrict__ B,
    const float* __restrict__ bias,
    int M, int N, int K)
{
    __shared__ float As[BK][BM];
    __shared__ float Bs[BK][BN];

    const int bx = blockIdx.x;   // n tile
    const int by = blockIdx.y;   // m tile
    const int tid = threadIdx.x;
    const int ty = tid >> 4;     // 0..15
    const int tx = tid & 15;     // 0..15

    const float* Ablk = A + (size_t)by * BM * K;
    const float* Bblk = B + (size_t)bx * BN;

    float acc[TM][TN];
    #pragma unroll
    for (int i = 0; i < TM; i++)
        #pragma unroll
        for (int j = 0; j < TN; j++)
            acc[i][j] = 0.0f;

    // Global->shared load indices
    const int arow = tid >> 2;          // 0..63 (and +64)
    const int acol = (tid & 3) * 4;     // 0,4,8,12
    const int brow = tid >> 5;          // 0..7 (and +8)
    const int bcol = (tid & 31) * 4;    // 0..124

    for (int k0 = 0; k0 < K; k0 += BK) {
        // A tile: 128 rows x 16 k, stored transposed As[k][m]
        float4 a0 = *(const float4*)(Ablk + (size_t)arow * K + k0 + acol);
        float4 a1 = *(const float4*)(Ablk + (size_t)(arow + 64) * K + k0 + acol);
        As[acol + 0][arow] = a0.x;
        As[acol + 1][arow] = a0.y;
        As[acol + 2][arow] = a0.z;
        As[acol + 3][arow] = a0.w;
        As[acol + 0][arow + 64] = a1.x;
        As[acol + 1][arow + 64] = a1.y;
        As[acol + 2][arow + 64] = a1.z;
        As[acol + 3][arow + 64] = a1.w;

        // B tile: 16 k x 128 n, stored direct Bs[k][n]
        float4 b0 = *(const float4*)(Bblk + (size_t)(k0 + brow) * N + bcol);
        float4 b1 = *(const float4*)(Bblk + (size_t)(k0 + brow + 8) * N + bcol);
        *(float4*)&Bs[brow][bcol]     = b0;
        *(float4*)&Bs[brow + 8][bcol] = b1;

        __syncthreads();

        #pragma unroll
        for (int kk = 0; kk < BK; kk++) {
            float a[TM], b[TN];
            *(float4*)&a[0] = *(const float4*)&As[kk][ty * TM];
            *(float4*)&a[4] = *(const float4*)&As[kk][ty * TM + 4];
            *(float4*)&b[0] = *(const float4*)&Bs[kk][tx * TN];
            *(float4*)&b[4] = *(const float4*)&Bs[kk][tx * TN + 4];
            #pragma unroll
            for (int i = 0; i < TM; i++)
                #pragma unroll
                for (int j = 0; j < TN; j++)
                    acc[i][j] = fmaf(a[i], b[j], acc[i][j]);
        }
        __syncthreads();
    }

    // Epilogue: add bias, write to g_pre
    const int cm = by * BM + ty * TM;
    const int cn = bx * BN + tx * TN;
    float4 bias0 = *(const float4*)(bias + cn);
    float4 bias1 = *(const float4*)(bias + cn + 4);
    #pragma unroll
    for (int i = 0; i < TM; i++) {
        float4 v0, v1;
        v0.x = acc[i][0] + bias0.x;
        v0.y = acc[i][1] + bias0.y;
        v0.z = acc[i][2] + bias0.z;
        v0.w = acc[i][3] + bias0.w;
        v1.x = acc[i][4] + bias1.x;
        v1.y = acc[i][5] + bias1.y;
        v1.z = acc[i][6] + bias1.z;
        v1.w = acc[i][7] + bias1.w;
        float* crow = g_pre + (size_t)(cm + i) * N + cn;
        *(float4*)(crow)     = v0;
        *(float4*)(crow + 4) = v1;
    }
}

// ---------------------------------------------------------------------------
// K2: per-row top-k via 4-pass byte radix-select on monotone uint keys.
// One block per row; row keys cached in dynamic smem (64 KB).
// ---------------------------------------------------------------------------
__global__ __launch_bounds__(256) void topk_kernel(int dsae, int k)
{
    extern __shared__ uint32_t skeys[];   // dsae keys
    __shared__ int hist[256];
    __shared__ uint32_t s_prefix;
    __shared__ int s_krem;
    __shared__ int s_cnt_gt, s_cnt_eq, s_m;

    const int row = blockIdx.x;
    const int tid = threadIdx.x;
    const float* pre = g_pre + (size_t)row * dsae;

    // Monotone map float -> uint (larger float => larger uint)
    for (int i = tid; i < dsae; i += blockDim.x) {
        uint32_t u = __float_as_uint(pre[i]);
        u = (u & 0x80000000u) ? ~u : (u | 0x80000000u);
        skeys[i] = u;
    }
    if (tid == 0) { s_prefix = 0u; s_krem = k; }
    __syncthreads();

    for (int pass = 0; pass < 4; pass++) {
        const int shift = 24 - 8 * pass;
        const uint32_t mask_hi = (pass == 0) ? 0u : (0xFFFFFFFFu << (shift + 8));

        if (tid < 256) hist[tid] = 0;
        __syncthreads();
        const uint32_t pref = s_prefix;
        for (int i = tid; i < dsae; i += blockDim.x) {
            uint32_t u = skeys[i];
            if ((u & mask_hi) == pref)
                atomicAdd(&hist[(u >> shift) & 0xFF], 1);
        }
        __syncthreads();
        if (tid == 0) {
            int cum = 0;
            int b = 255;
            for (; b > 0; b--) {
                int c = hist[b];
                if (cum + c >= s_krem) break;
                cum += c;
            }
            s_prefix = pref | ((uint32_t)b << shift);
            s_krem -= cum;
        }
        __syncthreads();
    }

    const uint32_t T = s_prefix;  // exact key of the k-th largest value
    if (tid == 0) { s_m = k - s_krem; s_cnt_gt = 0; s_cnt_eq = 0; }
    __syncthreads();
    const int m = s_m;   // count strictly greater than T

    for (int i = tid; i < dsae; i += blockDim.x) {
        uint32_t u = skeys[i];
        int slot = -1;
        if (u > T) {
            slot = atomicAdd(&s_cnt_gt, 1);
        } else if (u == T) {
            int p = atomicAdd(&s_cnt_eq, 1);
            if (m + p < k) slot = m + p;
        }
        if (slot >= 0) {
            uint32_t ob = (u & 0x80000000u) ? (u ^ 0x80000000u) : ~u;
            float f = __uint_as_float(ob);
            g_idx[row * k + slot] = i;
            g_val[row * k + slot] = fmaxf(f, 0.0f);   // ReLU on kept activations
        }
    }
}

// ---------------------------------------------------------------------------
// K3: sparse decode  recon[row] = sum_j val_j * W_dec[idx_j, :] + b_dec
// One block per row, 512 threads, 4 columns each via float4.
// ---------------------------------------------------------------------------
__global__ __launch_bounds__(512) void decode_kernel(
    const float* __restrict__ Wdec,
    const float* __restrict__ bdec,
    float* __restrict__ out,
    int din, int k)
{
    __shared__ int   sidx[KTOP];
    __shared__ float sval[KTOP];

    const int row = blockIdx.x;
    const int tid = threadIdx.x;
    if (tid < k) {
        sidx[tid] = g_idx[row * k + tid];
        sval[tid] = g_val[row * k + tid];
    }
    __syncthreads();

    const int c = tid * 4;
    if (c < din) {
        float4 acc = *(const float4*)(bdec + c);
        #pragma unroll 8
        for (int j = 0; j < KTOP; j++) {
            float v = sval[j];
            const float4 w = *(const float4*)(Wdec + (size_t)sidx[j] * din + c);
            acc.x = fmaf(v, w.x, acc.x);
            acc.y = fmaf(v, w.y, acc.y);
            acc.z = fmaf(v, w.z, acc.z);
            acc.w = fmaf(v, w.w, acc.w);
        }
        *(float4*)(out + (size_t)row * din + c) = acc;
    }
}

// ---------------------------------------------------------------------------
// Launch
// ---------------------------------------------------------------------------
extern "C" void kernel_launch(void* const* d_in, const int* in_sizes, int n_in,
                              void* d_out, int out_size)
{
    const float* x     = (const float*)d_in[0];
    const float* W_enc = (const float*)d_in[1];
    const float* W_dec = (const float*)d_in[2];
    const float* b_enc = (const float*)d_in[3];
    const float* b_dec = (const float*)d_in[4];
    // d_in[5] is k (device int); fixed to 64 by setup_inputs.

    const int din  = in_sizes[4];          // 2048
    const int dsae = in_sizes[3];          // 16384
    const int M    = in_sizes[0] / din;    // 8192
    float* out = (float*)d_out;

    // K1: encode GEMM (+bias) -> g_pre
    dim3 grid1(dsae / BN, M / BM);
    sgemm_bias_kernel<<<grid1, 256>>>(x, W_enc, b_enc, M, dsae, din);

    // K2: top-k per row (needs 64 KB dynamic smem)
    const size_t smem = (size_t)dsae * sizeof(uint32_t);
    cudaFuncSetAttribute(topk_kernel, cudaFuncAttributeMaxDynamicSharedMemorySize,
                         (int)smem);
    topk_kernel<<<M, 256, smem>>>(dsae, KTOP);

    // K3: sparse decode -> out
    decode_kernel<<<M, 512>>>(W_dec, b_dec, out, din, KTOP);
}